// round 6
// baseline (speedup 1.0000x reference)
#include <cuda_runtime.h>

#define NEG_INF __int_as_float(0xff800000)

// Tropical conv: out[b,o,y,x] = max_{c,dy,dx} img[b,c,y+dy-1,x+dx-1] + ker[o,c,2-dy,2-dx]
// B=8, C=32, H=W=32, O=32, 3x3, pad=1 (-inf)
//
// Grid: 512 blocks = 8 b x 16 og(2 o) x 4 row-strips(8 rows)
// Block: 256 thr = 8 warps = 2 o_local x 4 c-groups (8 ch each)
// Lane: y = lane>>2 (8 rows), xg = lane&3; thread computes 8 consecutive x px.
// Window loads are LDS.64 (conflict-free per half-warp phase at stride 34);
// adds are packed add.rn.f32x2 where pairs are even-aligned (dx=0,2).
// Halos (-inf) live in padded smem cols 0 and 33 -> no edge selects.

__device__ __forceinline__ float2 fadd2(float2 a, float2 b) {
    float2 c;
    asm("add.rn.f32x2 %0, %1, %2;"
        : "=l"(reinterpret_cast<unsigned long long&>(c))
        : "l"(reinterpret_cast<unsigned long long&>(a)),
          "l"(reinterpret_cast<unsigned long long&>(b)));
    return c;
}

__global__ __launch_bounds__(256) void bconv_kernel(
    const float* __restrict__ img,   // [8][32][32][32]
    const float* __restrict__ ker,   // [32][32][3][3]
    float* __restrict__ out)         // [8][32][32][32]
{
    // tile[c][r][s]: padded col s (actual col s-1); s=0 and s=33 are -inf halos.
    // stride 34 floats = 17 float2: LDS.64 bank-pair = (y + 4*xg) mod 16 -> bijective per phase.
    __shared__ __align__(16) float  tile[32][10][34];   // 43520 B
    __shared__ __align__(16) float2 kdup[32][9][2];     //  4608 B  (k,k) duplicated taps
    float* part = &tile[0][0][0];    // combine-phase overlay (dead tile)

    const int bx  = blockIdx.x;
    const int b   = bx >> 6;          // 0..7
    const int og  = (bx >> 2) & 15;   // 0..15
    const int ys  = bx & 3;           // 0..3
    const int y0  = ys << 3;
    const int tid = threadIdx.x;

    // ---- flipped kernel taps, duplicated into float2 ----
    for (int i = tid; i < 32 * 9 * 2; i += 256) {
        int ol = i & 1;
        int ct = i >> 1;
        int c  = ct / 9;
        int t  = ct - c * 9;
        float kv = ker[((og * 2 + ol) * 32 + c) * 9 + (8 - t)];
        kdup[c][t][ol] = make_float2(kv, kv);
    }

    // ---- stage image strip via float4 loads ----
    const float* imb = img + (b << 15);
    #pragma unroll
    for (int k = 0; k < 10; k++) {
        int fid = tid + (k << 8);          // 0..2559 float4 tiles
        int r   = fid >> 8;                // padded row 0..9
        int c   = (fid >> 3) & 31;         // channel
        int q   = fid & 7;                 // float4 within row
        int gy  = y0 + r - 1;
        float4 v = make_float4(NEG_INF, NEG_INF, NEG_INF, NEG_INF);
        if ((unsigned)gy < 32u)
            v = reinterpret_cast<const float4*>(imb + (c << 10) + (gy << 5))[q];
        float* dst = &tile[c][r][1 + (q << 2)];
        dst[0] = v.x; dst[1] = v.y; dst[2] = v.z; dst[3] = v.w;
    }
    // halo cols 0 and 33
    for (int h = tid; h < 320; h += 256) {
        int c = h >> 2;          // uses 320 = 32*10: c = h/10 needed -> do exact:
        c = h / 10;
        int r = h - c * 10;
        tile[c][r][0]  = NEG_INF;
        tile[c][r][33] = NEG_INF;
    }
    __syncthreads();

    const int wid  = tid >> 5;
    const int ol   = wid & 1;        // o_local (warp-uniform)
    const int g    = wid >> 1;       // c-group (warp-uniform)
    const int lane = tid & 31;
    const int y    = lane >> 2;      // local output row 0..7
    const int xg   = lane & 3;
    const int xb   = xg << 3;        // first pixel x
    const int xb2  = xg << 2;        // float2 offset within row

    float acc[8];
    #pragma unroll
    for (int p = 0; p < 8; p++) acc[p] = NEG_INF;

    const int c0 = g << 3;
    #pragma unroll 2
    for (int ci = 0; ci < 8; ci++) {
        const int c = c0 + ci;
        // window pairs P[dy][j2] = (win[2*j2], win[2*j2+1]), win[j] = padded col xb+j
        float2 P[3][5];
        #pragma unroll
        for (int dy = 0; dy < 3; dy++) {
            const float2* rp = reinterpret_cast<const float2*>(&tile[c][y + dy][0]);
            #pragma unroll
            for (int j2 = 0; j2 < 5; j2++)
                P[dy][j2] = rp[xb2 + j2];
        }

        #pragma unroll
        for (int t = 0; t < 9; t++) {
            const int dy = t / 3, dx = t % 3;
            const float2 kk = kdup[c][t][ol];   // broadcast LDS.64
            if (dx == 0) {
                #pragma unroll
                for (int h = 0; h < 4; h++) {
                    float2 r = fadd2(P[dy][h], kk);
                    acc[2*h]   = fmaxf(acc[2*h],   r.x);
                    acc[2*h+1] = fmaxf(acc[2*h+1], r.y);
                }
            } else if (dx == 2) {
                #pragma unroll
                for (int h = 0; h < 4; h++) {
                    float2 r = fadd2(P[dy][h + 1], kk);
                    acc[2*h]   = fmaxf(acc[2*h],   r.x);
                    acc[2*h+1] = fmaxf(acc[2*h+1], r.y);
                }
            } else {
                // odd offsets: scalar adds on pair halves (no repacking)
                const float kv = kk.x;
                float w[8];
                w[0] = P[dy][0].y; w[1] = P[dy][1].x; w[2] = P[dy][1].y; w[3] = P[dy][2].x;
                w[4] = P[dy][2].y; w[5] = P[dy][3].x; w[6] = P[dy][3].y; w[7] = P[dy][4].x;
                #pragma unroll
                for (int p = 0; p < 8; p++)
                    acc[p] = fmaxf(acc[p], w[p] + kv);
            }
        }
    }

    // ---- combine 4 c-group partials via smem overlay ----
    __syncthreads();
    if (g > 0) {
        float* dst = part + (((g - 1) * 2 + ol) * 32 + lane) * 9;  // stride 9: conflict-free
        #pragma unroll
        for (int p = 0; p < 8; p++) dst[p] = acc[p];
    }
    __syncthreads();
    if (g == 0) {
        #pragma unroll
        for (int gg = 0; gg < 3; gg++) {
            const float* src = part + ((gg * 2 + ol) * 32 + lane) * 9;
            #pragma unroll
            for (int p = 0; p < 8; p++)
                acc[p] = fmaxf(acc[p], src[p]);
        }
        const int o = (og << 1) + ol;
        float* op = out + (((b << 5) + o) << 10) + ((y0 + y) << 5) + xb;
        reinterpret_cast<float4*>(op)[0] = make_float4(acc[0], acc[1], acc[2], acc[3]);
        reinterpret_cast<float4*>(op)[1] = make_float4(acc[4], acc[5], acc[6], acc[7]);
    }
}

extern "C" void kernel_launch(void* const* d_in, const int* in_sizes, int n_in,
                              void* d_out, int out_size) {
    const float* img = (const float*)d_in[0];
    const float* ker = (const float*)d_in[1];
    float* outp = (float*)d_out;
    bconv_kernel<<<512, 256>>>(img, ker, outp);
}

// round 8
// speedup vs baseline: 1.0194x; 1.0194x over previous
#include <cuda_runtime.h>

#define NEG_INF __int_as_float(0xff800000)

// Tropical conv: out[b,o,y,x] = max_{c,dy,dx} img[b,c,y+dy-1,x+dx-1] + ker[o,c,2-dy,2-dx]
// B=8, C=32, H=W=32, O=32, 3x3, pad=1 (-inf)
//
// Grid: 512 blocks = 8 b x 16 og(2 o) x 4 row-strips(8 rows)
// Block: 256 thr = 8 warps = 8 c-groups (4 ch each); EACH THREAD accumulates
// BOTH o's of the og pair, so window LDS are amortized over 2x the math.
// Lane: y = lane>>2 (8 rows), xg = lane&3; thread computes 8 consecutive x px.
// Window loads: LDS.64, stride 34 floats -> conflict-free per half-warp phase.
// Packed add.rn.f32x2 for even-aligned taps (dx=0,2); scalar for dx=1.
// Halos (-inf) in padded smem cols 0 and 33 -> no edge selects.

__device__ __forceinline__ float2 fadd2(float2 a, float2 b) {
    float2 c;
    asm("add.rn.f32x2 %0, %1, %2;"
        : "=l"(reinterpret_cast<unsigned long long&>(c))
        : "l"(reinterpret_cast<unsigned long long&>(a)),
          "l"(reinterpret_cast<unsigned long long&>(b)));
    return c;
}

__global__ __launch_bounds__(256) void bconv_kernel(
    const float* __restrict__ img,   // [8][32][32][32]
    const float* __restrict__ ker,   // [32][32][3][3]
    float* __restrict__ out)         // [8][32][32][32]
{
    // tile[c][r][s]: padded col s (actual col s-1); s=0 and s=33 are -inf halos.
    __shared__ __align__(16) float tile[32][10][34];   // 43520 B
    __shared__ float ksm[32][9][2];                    //  2304 B : flipped taps per o_local
    float* part = &tile[0][0][0];    // combine-phase overlay (dead tile)

    const int bx  = blockIdx.x;
    const int b   = bx >> 6;          // 0..7
    const int og  = (bx >> 2) & 15;   // 0..15
    const int ys  = bx & 3;           // 0..3
    const int y0  = ys << 3;
    const int tid = threadIdx.x;

    // ---- flipped kernel taps ----
    for (int i = tid; i < 32 * 9 * 2; i += 256) {
        int ol = i & 1;
        int ct = i >> 1;
        int c  = ct / 9;
        int t  = ct - c * 9;
        ksm[c][t][ol] = ker[((og * 2 + ol) * 32 + c) * 9 + (8 - t)];
    }

    // ---- stage image strip: scalar, coalesced LDG.32 + conflict-free STS.32 ----
    const float* imb = img + (b << 15);
    #pragma unroll
    for (int k = 0; k < 40; k++) {
        int i  = tid + (k << 8);       // 0..10239
        int r  = i >> 10;              // padded row 0..9
        int c  = (i >> 5) & 31;        // channel
        int cc = i & 31;               // actual col (lane-consecutive)
        int gy = y0 + r - 1;
        float v = NEG_INF;
        if ((unsigned)gy < 32u)
            v = imb[(c << 10) + (gy << 5) + cc];
        tile[c][r][cc + 1] = v;
    }
    for (int h = tid; h < 320; h += 256) {   // halo cols 0 and 33
        int c = h / 10;
        int r = h - c * 10;
        tile[c][r][0]  = NEG_INF;
        tile[c][r][33] = NEG_INF;
    }
    __syncthreads();

    const int g    = tid >> 5;       // c-group 0..7 (warp-uniform)
    const int lane = tid & 31;
    const int y    = lane >> 2;      // local output row 0..7
    const int xg   = lane & 3;
    const int xb   = xg << 3;        // first pixel x
    const int xb2  = xg << 2;        // float2 offset within padded row

    float acc0[8], acc1[8];
    #pragma unroll
    for (int p = 0; p < 8; p++) { acc0[p] = NEG_INF; acc1[p] = NEG_INF; }

    const int c0 = g << 2;
    #pragma unroll 1
    for (int ci = 0; ci < 4; ci++) {
        const int c = c0 + ci;
        // window pairs P[dy][j2] covering padded cols xb..xb+9, rows y..y+2
        float2 P[3][5];
        #pragma unroll
        for (int dy = 0; dy < 3; dy++) {
            const float2* rp = reinterpret_cast<const float2*>(&tile[c][y + dy][0]);
            #pragma unroll
            for (int j2 = 0; j2 < 5; j2++)
                P[dy][j2] = rp[xb2 + j2];
        }

        #pragma unroll
        for (int t = 0; t < 9; t++) {
            const int dy = t / 3, dx = t % 3;
            const float k0 = ksm[c][t][0];   // broadcast LDS.32 (1 wv)
            const float k1 = ksm[c][t][1];
            if (dx != 1) {
                const int off = (dx == 2) ? 1 : 0;
                const float2 kk0 = make_float2(k0, k0);   // 1 MOV each
                const float2 kk1 = make_float2(k1, k1);
                #pragma unroll
                for (int h = 0; h < 4; h++) {
                    float2 r0 = fadd2(P[dy][h + off], kk0);
                    acc0[2*h]   = fmaxf(acc0[2*h],   r0.x);
                    acc0[2*h+1] = fmaxf(acc0[2*h+1], r0.y);
                    float2 r1 = fadd2(P[dy][h + off], kk1);
                    acc1[2*h]   = fmaxf(acc1[2*h],   r1.x);
                    acc1[2*h+1] = fmaxf(acc1[2*h+1], r1.y);
                }
            } else {
                float w[8];
                w[0] = P[dy][0].y; w[1] = P[dy][1].x; w[2] = P[dy][1].y; w[3] = P[dy][2].x;
                w[4] = P[dy][2].y; w[5] = P[dy][3].x; w[6] = P[dy][3].y; w[7] = P[dy][4].x;
                #pragma unroll
                for (int p = 0; p < 8; p++) {
                    acc0[p] = fmaxf(acc0[p], w[p] + k0);
                    acc1[p] = fmaxf(acc1[p], w[p] + k1);
                }
            }
        }
    }

    // ---- combine the 8 c-group partials via smem overlay (stride 9: bank-free) ----
    __syncthreads();   // everyone done reading tile
    if (g > 0) {
        float* dst = part + (((g - 1) * 2 + 0) * 32 + lane) * 9;
        #pragma unroll
        for (int p = 0; p < 8; p++) dst[p] = acc0[p];
        dst = part + (((g - 1) * 2 + 1) * 32 + lane) * 9;
        #pragma unroll
        for (int p = 0; p < 8; p++) dst[p] = acc1[p];
    }
    __syncthreads();
    if (g == 0) {
        #pragma unroll
        for (int gg = 0; gg < 7; gg++) {
            const float* s0 = part + ((gg * 2 + 0) * 32 + lane) * 9;
            const float* s1 = part + ((gg * 2 + 1) * 32 + lane) * 9;
            #pragma unroll
            for (int p = 0; p < 8; p++) {
                acc0[p] = fmaxf(acc0[p], s0[p]);
                acc1[p] = fmaxf(acc1[p], s1[p]);
            }
        }
        const int o0 = og << 1;
        float* op0 = out + (((b << 5) + o0) << 10) + ((y0 + y) << 5) + xb;
        float* op1 = op0 + 1024;   // o0+1
        reinterpret_cast<float4*>(op0)[0] = make_float4(acc0[0], acc0[1], acc0[2], acc0[3]);
        reinterpret_cast<float4*>(op0)[1] = make_float4(acc0[4], acc0[5], acc0[6], acc0[7]);
        reinterpret_cast<float4*>(op1)[0] = make_float4(acc1[0], acc1[1], acc1[2], acc1[3]);
        reinterpret_cast<float4*>(op1)[1] = make_float4(acc1[4], acc1[5], acc1[6], acc1[7]);
    }
}

extern "C" void kernel_launch(void* const* d_in, const int* in_sizes, int n_in,
                              void* d_out, int out_size) {
    const float* img = (const float*)d_in[0];
    const float* ker = (const float*)d_in[1];
    float* outp = (float*)d_out;
    bconv_kernel<<<512, 256>>>(img, ker, outp);
}